// round 13
// baseline (speedup 1.0000x reference)
#include <cuda_runtime.h>
#include <cuda_bf16.h>
#include <cstddef>
#include <cstdint>

// Two-layer LSTM recurrence, persistent kernel, TENSOR-CORE layer-1 GEMV.
// R13 = R12 (20 compute warps x m-split, fused split-bf16 mma.m16n8k16)
// with full double-buffering of h (Ash) and c1 so the OBSERVED phase runs
// with a SINGLE barrier per step (GEMM, layer-2, and epilogue overlap).
// Space for the second buffers comes from dropping dead padding: WSTR 112,
// and the lo-precision correction is dropped for k-cols 96..111 (4 real
// columns lose ~2^-9 relative correction -> negligible vs 1e-3 budget).
//
// 128 blocks x 672 threads:
//   warps 0-19 : compute. g = wid>>1 (n-group), mt = wid&1 (m-tile).
//   warp 20    : layer-2 (lane = batch elem), one step behind.

#define CELL     100
#define NB       32
#define THREADS  672
#define L2BASE   640
#define ASTRIDE  216      // bf16/row: hi 0-111, lo 112-207 (96 cols)
#define ALO      112
#define WSTR     112      // Whi row stride (bf16)
#define WLOSTR   96       // Wlo row stride (bf16)
#define CSTR     101      // c1 row stride (floats), [batch][unit]
#define ABUF     (32 * ASTRIDE)   // bf16 elems per A buffer
#define CBUF     (32 * CSTR)      // floats per c1 buffer

#define LDSM_X4(r0,r1,r2,r3, addr) \
  asm volatile("ldmatrix.sync.aligned.m8n8.x4.shared.b16 {%0,%1,%2,%3}, [%4];" \
    : "=r"(r0), "=r"(r1), "=r"(r2), "=r"(r3) : "r"(addr))
#define LDSM_X2(r0,r1, addr) \
  asm volatile("ldmatrix.sync.aligned.m8n8.x2.shared.b16 {%0,%1}, [%2];" \
    : "=r"(r0), "=r"(r1) : "r"(addr))
#define MMA16816(d, a0,a1,a2,a3, b0,b1) \
  asm volatile("mma.sync.aligned.m16n8k16.row.col.f32.bf16.bf16.f32 " \
    "{%0,%1,%2,%3}, {%4,%5,%6,%7}, {%8,%9}, {%0,%1,%2,%3};" \
    : "+f"((d)[0]), "+f"((d)[1]), "+f"((d)[2]), "+f"((d)[3]) \
    : "r"(a0), "r"(a1), "r"(a2), "r"(a3), "r"(b0), "r"(b1))

__device__ __forceinline__ float rcp_approx(float x) {
    float r;
    asm("rcp.approx.f32 %0, %1;" : "=f"(r) : "f"(x));
    return r;
}
// ---- fast path (compute warps): single-MUFU HW tanh ----
__device__ __forceinline__ float tanh_hw(float x) {
    float r;
    asm("tanh.approx.f32 %0, %1;" : "=f"(r) : "f"(x));
    return r;
}
__device__ __forceinline__ float sigm_fast(float x) {
    return fmaf(0.5f, tanh_hw(0.5f * x), 0.5f);
}
// ---- exact path (layer-2 warp) ----
__device__ __forceinline__ float sigm(float x) {
    return rcp_approx(1.0f + __expf(-x));
}
__device__ __forceinline__ float tanh_f(float x) {
    float e = __expf(2.0f * x);
    return fmaf(-2.0f, rcp_approx(e + 1.0f), 1.0f);
}
__device__ __forceinline__ uint32_t smem_u32(const void* p) {
    return (uint32_t)__cvta_generic_to_shared(p);
}

__global__ void __launch_bounds__(THREADS, 1)
tsrnn_kernel(const float* __restrict__ input,
             const float* __restrict__ W_ih1, const float* __restrict__ W_hh1,
             const float* __restrict__ b_ih1, const float* __restrict__ b_hh1,
             const float* __restrict__ W_ih2, const float* __restrict__ W_hh2,
             const float* __restrict__ b_ih2, const float* __restrict__ b_hh2,
             float* __restrict__ out, int T, int FUT, int Btot)
{
    extern __shared__ char smem[];
    __nv_bfloat16* Whi = (__nv_bfloat16*)smem;          // [400][112]  row n = 4u+k
    __nv_bfloat16* Wlo = Whi + 400 * WSTR;              // [400][96]
    __nv_bfloat16* Ash = Wlo + 400 * WLOSTR;            // [2][32][216]
    float* c1sh   = (float*)(Ash + 2 * ABUF);           // [2][32][101]
    float* w2i    = c1sh + 2 * CBUF;                    // [100][4]
    float* wih_sh = w2i + 400;                          // [100][4]
    float* bsum_sh= wih_sh + 400;                       // [100][4]
    float* xsh    = bsum_sh + 400;                      // [32] (future phase)

    const int tid    = threadIdx.x;
    const int bglob0 = blockIdx.x * NB;
    const int wid    = tid >> 5;
    const int lane   = tid & 31;

    // ================= staging =================
    for (int idx = tid; idx < 400 * WSTR; idx += THREADS) {
        int n = idx / WSTR, kk = idx - n * WSTR;
        int u = n >> 2, k = n & 3;
        float w = (kk < CELL) ? W_hh1[(k * CELL + u) * CELL + kk] : 0.0f;
        Whi[idx] = __float2bfloat16(w);
    }
    for (int idx = tid; idx < 400 * WLOSTR; idx += THREADS) {
        int n = idx / WLOSTR, kk = idx - n * WLOSTR;   // kk < 96 < 100
        int u = n >> 2, k = n & 3;
        float w = W_hh1[(k * CELL + u) * CELL + kk];
        Wlo[idx] = __float2bfloat16(w - __bfloat162float(__float2bfloat16(w)));
    }
    for (int idx = tid; idx < 2 * ABUF; idx += THREADS)
        Ash[idx] = __float2bfloat16(0.0f);
    for (int idx = tid; idx < 2 * CBUF; idx += THREADS) c1sh[idx] = 0.0f;
    for (int idx = tid; idx < 400; idx += THREADS) {
        int u = idx >> 2, k = idx & 3;
        w2i[idx]    = W_ih2[k * CELL + u];
        wih_sh[idx] = W_ih1[k * CELL + u];
        bsum_sh[idx]= b_ih1[k * CELL + u] + b_hh1[k * CELL + u];
    }
    if (tid < NB) xsh[tid] = 0.0f;

    // ================= per-thread setup =================
    const bool cw = (wid < 20);                 // compute warp
    const bool l2 = (tid >= L2BASE);            // warp 20
    const int  g  = wid >> 1;                   // n-group (0..9)
    const int  mt = wid & 1;                    // m-tile (0..1)
    const int  q  = lane & 3;
    const int  pp = q & 1;                      // 0: holds (i,f); 1: holds (g,o)
    const int  rowbase = lane >> 2;
    const int  rowm = mt * 16 + rowbase + (pp ? 8 : 0);  // this thread's batch row

    // ldmatrix lane addresses (byte offsets precomputed)
    const uint32_t Au32  = smem_u32(Ash);
    const uint32_t Whi32 = smem_u32(Whi);
    const uint32_t Wlo32 = smem_u32(Wlo);
    uint32_t aaddr[2], bph[2], bpl[2], bs4h = 0, bs4l = 0;
    if (cw) {
        // A: 16 rows of own m-tile, both k-halves, per buffer
        const uint32_t arow = ((mt * 16 + (lane & 15)) * ASTRIDE + (lane >> 4) * 8) * 2;
        aaddr[0] = Au32 + arow;
        aaddr[1] = Au32 + ABUF * 2 + arow;
        // B pairs: x4 loads n-tiles (5g+2j, 5g+2j+1), both k-halves
        const int sub = lane >> 3, l8 = lane & 7;
        const int ntoff = sub >> 1, khalf = sub & 1;
        #pragma unroll
        for (int j = 0; j < 2; j++) {
            int nt = 5 * g + 2 * j + ntoff;
            bph[j] = Whi32 + ((8 * nt + l8) * WSTR   + khalf * 8) * 2;
            bpl[j] = Wlo32 + ((8 * nt + l8) * WLOSTR + khalf * 8) * 2;
        }
        // B single: n-tile 5g+4 (x2: lanes 0-15, two k-halves)
        const int l4 = lane & 15;
        bs4h = Whi32 + ((8 * (5 * g + 4) + (l4 & 7)) * WSTR   + ((l4 >> 3) & 1) * 8) * 2;
        bs4l = Wlo32 + ((8 * (5 * g + 4) + (l4 & 7)) * WLOSTR + ((l4 >> 3) & 1) * 8) * 2;
    }

    // layer-2 per-lane constants + state
    const int bl2 = tid - L2BASE;
    float whh2[4], b2c[4];
    float h2 = 0.0f, c2 = 0.0f;
    if (l2) {
        #pragma unroll
        for (int k = 0; k < 4; k++) {
            whh2[k] = W_hh2[k];
            b2c[k]  = b_ih2[k] + b_hh2[k];
        }
    }

    float c1r[5];
    #pragma unroll
    for (int i = 0; i < 5; i++) c1r[i] = 0.0f;

    __syncthreads();

    // ================= main loop =================
    const int TOT = T + FUT;
    for (int t = 0; t < TOT; ++t) {
        const bool fut = (t >= T);
        const int p = t & 1;          // A buffer holding h[t-1]; c1[t] -> buf p
        float d[5][4];
        float xv = 0.0f;

        if (cw) {
            // ---- x prefetch (observed): LDG issued before the GEMM ----
            if (!fut) {
                xv = __ldg(input + (size_t)t * Btot + bglob0 + rowm);
            }

            // ---- fused split-bf16 GEMM on h[t-1] (buffer p) ----
            #pragma unroll
            for (int i = 0; i < 5; i++)
                #pragma unroll
                for (int r = 0; r < 4; r++) d[i][r] = 0.0f;

            const uint32_t ah_base = aaddr[p];

            #pragma unroll
            for (int kk = 0; kk < 6; kk++) {
                const uint32_t off = (uint32_t)(kk * 32);   // 16 cols * 2B

                uint32_t ah[4], al[4];
                LDSM_X4(ah[0], ah[1], ah[2], ah[3], ah_base + off);
                LDSM_X4(al[0], al[1], al[2], al[3], ah_base + ALO * 2 + off);

                #pragma unroll
                for (int j = 0; j < 2; j++) {
                    uint32_t bh0, bh1, bh2, bh3;
                    LDSM_X4(bh0, bh1, bh2, bh3, bph[j] + off);
                    MMA16816(d[2*j],   ah[0], ah[1], ah[2], ah[3], bh0, bh1);
                    MMA16816(d[2*j],   al[0], al[1], al[2], al[3], bh0, bh1);
                    MMA16816(d[2*j+1], ah[0], ah[1], ah[2], ah[3], bh2, bh3);
                    MMA16816(d[2*j+1], al[0], al[1], al[2], al[3], bh2, bh3);
                    uint32_t bl0, bl1, bl2r, bl3;
                    LDSM_X4(bl0, bl1, bl2r, bl3, bpl[j] + off);
                    MMA16816(d[2*j],   ah[0], ah[1], ah[2], ah[3], bl0, bl1);
                    MMA16816(d[2*j+1], ah[0], ah[1], ah[2], ah[3], bl2r, bl3);
                }
                {
                    uint32_t b0, b1;
                    LDSM_X2(b0, b1, bs4h + off);
                    MMA16816(d[4], ah[0], ah[1], ah[2], ah[3], b0, b1);
                    MMA16816(d[4], al[0], al[1], al[2], al[3], b0, b1);
                    uint32_t c0, c1v;
                    LDSM_X2(c0, c1v, bs4l + off);
                    MMA16816(d[4], ah[0], ah[1], ah[2], ah[3], c0, c1v);
                }
            }
            {   // kk = 6: hi*hi only (cols 96-111; lo corrections dropped)
                const uint32_t off = 6u * 32u;
                uint32_t ah[4];
                LDSM_X4(ah[0], ah[1], ah[2], ah[3], ah_base + off);
                #pragma unroll
                for (int j = 0; j < 2; j++) {
                    uint32_t bh0, bh1, bh2, bh3;
                    LDSM_X4(bh0, bh1, bh2, bh3, bph[j] + off);
                    MMA16816(d[2*j],   ah[0], ah[1], ah[2], ah[3], bh0, bh1);
                    MMA16816(d[2*j+1], ah[0], ah[1], ah[2], ah[3], bh2, bh3);
                }
                uint32_t b0, b1;
                LDSM_X2(b0, b1, bs4h + off);
                MMA16816(d[4], ah[0], ah[1], ah[2], ah[3], b0, b1);
            }
        } else if (l2) {
            // ---- layer-2 for step t-1 (reads c1 buffer (t-1)&1) ----
            if (t > 0) {
                const int tt = t - 1;
                const float* cp = c1sh + ((t - 1) & 1) * CBUF + bl2 * CSTR;
                float di = 0.f, df = 0.f, dg = 0.f, dz = 0.f;
                #pragma unroll 10
                for (int uu = 0; uu < CELL; uu++) {
                    float cv  = cp[uu];
                    float4 w4 = *(const float4*)(w2i + uu * 4);
                    di = fmaf(cv, w4.x, di);
                    df = fmaf(cv, w4.y, df);
                    dg = fmaf(cv, w4.z, dg);
                    dz = fmaf(cv, w4.w, dz);
                }
                float pi = fmaf(h2, whh2[0], di + b2c[0]);
                float pf = fmaf(h2, whh2[1], df + b2c[1]);
                float pg = fmaf(h2, whh2[2], dg + b2c[2]);
                float po = fmaf(h2, whh2[3], dz + b2c[3]);
                float c  = sigm(pf) * c2 + sigm(pi) * tanh_f(pg);
                c2 = c;
                h2 = sigm(po) * tanh_f(c);
                if (t >= T) xsh[bl2] = c;               // x for future step t
                if (tt >= T) out[(size_t)(bglob0 + bl2) * FUT + (tt - T)] = c;
            }
        }

        // future phase needs c2[t-1] (xsh) before the epilogue
        if (fut) __syncthreads();

        if (cw) {
            if (fut) xv = xsh[rowm];
            // ---- epilogue: writes A buffer p^1 and c1 buffer p ----
            __nv_bfloat16* aw = Ash + (p ^ 1) * ABUF + rowm * ASTRIDE;
            float*         cwv = c1sh + p * CBUF + rowm * CSTR;
            #pragma unroll
            for (int i = 0; i < 5; i++) {
                const int u = 2 * (5 * g + i) + (q >> 1);
                float* dd = d[i];
                // exchange with lane^1: even keeps row r, odd keeps row r+8
                float g0 = pp ? dd[0] : dd[2];
                float g1 = pp ? dd[1] : dd[3];
                float r0 = __shfl_xor_sync(0xffffffffu, g0, 1);
                float r1 = __shfl_xor_sync(0xffffffffu, g1, 1);
                float gi, gf, gg, go;
                if (!pp) { gi = dd[0]; gf = dd[1]; gg = r0;    go = r1;    }
                else     { gi = r0;    gf = r1;    gg = dd[2]; go = dd[3]; }

                const float4 bs = *(const float4*)(bsum_sh + u * 4);
                const float4 wi = *(const float4*)(wih_sh + u * 4);
                float pi = fmaf(xv, wi.x, gi + bs.x);
                float pf = fmaf(xv, wi.y, gf + bs.y);
                float pg = fmaf(xv, wi.z, gg + bs.z);
                float po = fmaf(xv, wi.w, go + bs.w);
                float c = sigm_fast(pf) * c1r[i] + sigm_fast(pi) * tanh_hw(pg);
                c1r[i] = c;
                float h = sigm_fast(po) * tanh_hw(c);

                cwv[u] = c;
                __nv_bfloat16 hh = __float2bfloat16(h);
                aw[u] = hh;
                if (u < 96)
                    aw[ALO + u] = __float2bfloat16(h - __bfloat162float(hh));
            }
        }

        __syncthreads();   // step boundary: all buffers published
    }

    // drain: layer-2 for the final step TOT-1
    if (l2) {
        const int tt = TOT - 1;
        const float* cp = c1sh + ((TOT - 1) & 1) * CBUF + bl2 * CSTR;
        float di = 0.f, df = 0.f, dg = 0.f, dz = 0.f;
        #pragma unroll 10
        for (int uu = 0; uu < CELL; uu++) {
            float cv  = cp[uu];
            float4 w4 = *(const float4*)(w2i + uu * 4);
            di = fmaf(cv, w4.x, di);
            df = fmaf(cv, w4.y, df);
            dg = fmaf(cv, w4.z, dg);
            dz = fmaf(cv, w4.w, dz);
        }
        float pi = fmaf(h2, whh2[0], di + b2c[0]);
        float pf = fmaf(h2, whh2[1], df + b2c[1]);
        float pg = fmaf(h2, whh2[2], dg + b2c[2]);
        float po = fmaf(h2, whh2[3], dz + b2c[3]);
        float c  = sigm(pf) * c2 + sigm(pi) * tanh_f(pg);
        out[(size_t)(bglob0 + bl2) * FUT + (tt - T)] = c;
    }
}

extern "C" void kernel_launch(void* const* d_in, const int* in_sizes, int n_in,
                              void* d_out, int out_size)
{
    const float* input = (const float*)d_in[0];
    const float* W_ih1 = (const float*)d_in[1];
    const float* W_hh1 = (const float*)d_in[2];
    const float* b_ih1 = (const float*)d_in[3];
    const float* b_hh1 = (const float*)d_in[4];
    const float* W_ih2 = (const float*)d_in[5];
    const float* W_hh2 = (const float*)d_in[6];
    const float* b_ih2 = (const float*)d_in[7];
    const float* b_hh2 = (const float*)d_in[8];
    float* out = (float*)d_out;

    const int Btot = 4096;
    const int T    = in_sizes[0] / Btot;   // 512
    const int FUT  = out_size   / Btot;    // 64

    const int smem = (400 * WSTR + 400 * WLOSTR + 2 * ABUF) * 2   // bf16 regions
                   + (2 * CBUF + 400 * 3 + NB) * 4;               // fp32 regions
                   // = (44800+38400+13824)*2 + (6464+1232)*4 = 224,832 B

    cudaFuncSetAttribute(tsrnn_kernel,
                         cudaFuncAttributeMaxDynamicSharedMemorySize, smem);

    tsrnn_kernel<<<Btot / NB, THREADS, smem>>>(
        input, W_ih1, W_hh1, b_ih1, b_hh1,
        W_ih2, W_hh2, b_ih2, b_hh2,
        out, T, FUT, Btot);
}

// round 14
// speedup vs baseline: 1.0002x; 1.0002x over previous
#include <cuda_runtime.h>
#include <cuda_bf16.h>
#include <cstddef>
#include <cstdint>

// Two-layer LSTM recurrence, persistent kernel, TENSOR-CORE layer-1 GEMV.
// R13 = R12 (20 compute warps x m-split, fused split-bf16 mma.m16n8k16)
// with full double-buffering of h (Ash) and c1 so the OBSERVED phase runs
// with a SINGLE barrier per step (GEMM, layer-2, and epilogue overlap).
// Space for the second buffers comes from dropping dead padding: WSTR 112,
// and the lo-precision correction is dropped for k-cols 96..111 (4 real
// columns lose ~2^-9 relative correction -> negligible vs 1e-3 budget).
//
// 128 blocks x 672 threads:
//   warps 0-19 : compute. g = wid>>1 (n-group), mt = wid&1 (m-tile).
//   warp 20    : layer-2 (lane = batch elem), one step behind.

#define CELL     100
#define NB       32
#define THREADS  672
#define L2BASE   640
#define ASTRIDE  216      // bf16/row: hi 0-111, lo 112-207 (96 cols)
#define ALO      112
#define WSTR     112      // Whi row stride (bf16)
#define WLOSTR   96       // Wlo row stride (bf16)
#define CSTR     101      // c1 row stride (floats), [batch][unit]
#define ABUF     (32 * ASTRIDE)   // bf16 elems per A buffer
#define CBUF     (32 * CSTR)      // floats per c1 buffer

#define LDSM_X4(r0,r1,r2,r3, addr) \
  asm volatile("ldmatrix.sync.aligned.m8n8.x4.shared.b16 {%0,%1,%2,%3}, [%4];" \
    : "=r"(r0), "=r"(r1), "=r"(r2), "=r"(r3) : "r"(addr))
#define LDSM_X2(r0,r1, addr) \
  asm volatile("ldmatrix.sync.aligned.m8n8.x2.shared.b16 {%0,%1}, [%2];" \
    : "=r"(r0), "=r"(r1) : "r"(addr))
#define MMA16816(d, a0,a1,a2,a3, b0,b1) \
  asm volatile("mma.sync.aligned.m16n8k16.row.col.f32.bf16.bf16.f32 " \
    "{%0,%1,%2,%3}, {%4,%5,%6,%7}, {%8,%9}, {%0,%1,%2,%3};" \
    : "+f"((d)[0]), "+f"((d)[1]), "+f"((d)[2]), "+f"((d)[3]) \
    : "r"(a0), "r"(a1), "r"(a2), "r"(a3), "r"(b0), "r"(b1))

__device__ __forceinline__ float rcp_approx(float x) {
    float r;
    asm("rcp.approx.f32 %0, %1;" : "=f"(r) : "f"(x));
    return r;
}
// ---- fast path (compute warps): single-MUFU HW tanh ----
__device__ __forceinline__ float tanh_hw(float x) {
    float r;
    asm("tanh.approx.f32 %0, %1;" : "=f"(r) : "f"(x));
    return r;
}
__device__ __forceinline__ float sigm_fast(float x) {
    return fmaf(0.5f, tanh_hw(0.5f * x), 0.5f);
}
// ---- exact path (layer-2 warp) ----
__device__ __forceinline__ float sigm(float x) {
    return rcp_approx(1.0f + __expf(-x));
}
__device__ __forceinline__ float tanh_f(float x) {
    float e = __expf(2.0f * x);
    return fmaf(-2.0f, rcp_approx(e + 1.0f), 1.0f);
}
__device__ __forceinline__ uint32_t smem_u32(const void* p) {
    return (uint32_t)__cvta_generic_to_shared(p);
}

__global__ void __launch_bounds__(THREADS, 1)
tsrnn_kernel(const float* __restrict__ input,
             const float* __restrict__ W_ih1, const float* __restrict__ W_hh1,
             const float* __restrict__ b_ih1, const float* __restrict__ b_hh1,
             const float* __restrict__ W_ih2, const float* __restrict__ W_hh2,
             const float* __restrict__ b_ih2, const float* __restrict__ b_hh2,
             float* __restrict__ out, int T, int FUT, int Btot)
{
    extern __shared__ char smem[];
    __nv_bfloat16* Whi = (__nv_bfloat16*)smem;          // [400][112]  row n = 4u+k
    __nv_bfloat16* Wlo = Whi + 400 * WSTR;              // [400][96]
    __nv_bfloat16* Ash = Wlo + 400 * WLOSTR;            // [2][32][216]
    float* c1sh   = (float*)(Ash + 2 * ABUF);           // [2][32][101]
    float* w2i    = c1sh + 2 * CBUF;                    // [100][4]
    float* wih_sh = w2i + 400;                          // [100][4]
    float* bsum_sh= wih_sh + 400;                       // [100][4]
    float* xsh    = bsum_sh + 400;                      // [32] (future phase)

    const int tid    = threadIdx.x;
    const int bglob0 = blockIdx.x * NB;
    const int wid    = tid >> 5;
    const int lane   = tid & 31;

    // ================= staging =================
    for (int idx = tid; idx < 400 * WSTR; idx += THREADS) {
        int n = idx / WSTR, kk = idx - n * WSTR;
        int u = n >> 2, k = n & 3;
        float w = (kk < CELL) ? W_hh1[(k * CELL + u) * CELL + kk] : 0.0f;
        Whi[idx] = __float2bfloat16(w);
    }
    for (int idx = tid; idx < 400 * WLOSTR; idx += THREADS) {
        int n = idx / WLOSTR, kk = idx - n * WLOSTR;   // kk < 96 < 100
        int u = n >> 2, k = n & 3;
        float w = W_hh1[(k * CELL + u) * CELL + kk];
        Wlo[idx] = __float2bfloat16(w - __bfloat162float(__float2bfloat16(w)));
    }
    for (int idx = tid; idx < 2 * ABUF; idx += THREADS)
        Ash[idx] = __float2bfloat16(0.0f);
    for (int idx = tid; idx < 2 * CBUF; idx += THREADS) c1sh[idx] = 0.0f;
    for (int idx = tid; idx < 400; idx += THREADS) {
        int u = idx >> 2, k = idx & 3;
        w2i[idx]    = W_ih2[k * CELL + u];
        wih_sh[idx] = W_ih1[k * CELL + u];
        bsum_sh[idx]= b_ih1[k * CELL + u] + b_hh1[k * CELL + u];
    }
    if (tid < NB) xsh[tid] = 0.0f;

    // ================= per-thread setup =================
    const bool cw = (wid < 20);                 // compute warp
    const bool l2 = (tid >= L2BASE);            // warp 20
    const int  g  = wid >> 1;                   // n-group (0..9)
    const int  mt = wid & 1;                    // m-tile (0..1)
    const int  q  = lane & 3;
    const int  pp = q & 1;                      // 0: holds (i,f); 1: holds (g,o)
    const int  rowbase = lane >> 2;
    const int  rowm = mt * 16 + rowbase + (pp ? 8 : 0);  // this thread's batch row

    // ldmatrix lane addresses (byte offsets precomputed)
    const uint32_t Au32  = smem_u32(Ash);
    const uint32_t Whi32 = smem_u32(Whi);
    const uint32_t Wlo32 = smem_u32(Wlo);
    uint32_t aaddr[2], bph[2], bpl[2], bs4h = 0, bs4l = 0;
    if (cw) {
        // A: 16 rows of own m-tile, both k-halves, per buffer
        const uint32_t arow = ((mt * 16 + (lane & 15)) * ASTRIDE + (lane >> 4) * 8) * 2;
        aaddr[0] = Au32 + arow;
        aaddr[1] = Au32 + ABUF * 2 + arow;
        // B pairs: x4 loads n-tiles (5g+2j, 5g+2j+1), both k-halves
        const int sub = lane >> 3, l8 = lane & 7;
        const int ntoff = sub >> 1, khalf = sub & 1;
        #pragma unroll
        for (int j = 0; j < 2; j++) {
            int nt = 5 * g + 2 * j + ntoff;
            bph[j] = Whi32 + ((8 * nt + l8) * WSTR   + khalf * 8) * 2;
            bpl[j] = Wlo32 + ((8 * nt + l8) * WLOSTR + khalf * 8) * 2;
        }
        // B single: n-tile 5g+4 (x2: lanes 0-15, two k-halves)
        const int l4 = lane & 15;
        bs4h = Whi32 + ((8 * (5 * g + 4) + (l4 & 7)) * WSTR   + ((l4 >> 3) & 1) * 8) * 2;
        bs4l = Wlo32 + ((8 * (5 * g + 4) + (l4 & 7)) * WLOSTR + ((l4 >> 3) & 1) * 8) * 2;
    }

    // layer-2 per-lane constants + state
    const int bl2 = tid - L2BASE;
    float whh2[4], b2c[4];
    float h2 = 0.0f, c2 = 0.0f;
    if (l2) {
        #pragma unroll
        for (int k = 0; k < 4; k++) {
            whh2[k] = W_hh2[k];
            b2c[k]  = b_ih2[k] + b_hh2[k];
        }
    }

    float c1r[5];
    #pragma unroll
    for (int i = 0; i < 5; i++) c1r[i] = 0.0f;

    __syncthreads();

    // ================= main loop =================
    const int TOT = T + FUT;
    for (int t = 0; t < TOT; ++t) {
        const bool fut = (t >= T);
        const int p = t & 1;          // A buffer holding h[t-1]; c1[t] -> buf p
        float d[5][4];
        float xv = 0.0f;

        if (cw) {
            // ---- x prefetch (observed): LDG issued before the GEMM ----
            if (!fut) {
                xv = __ldg(input + (size_t)t * Btot + bglob0 + rowm);
            }

            // ---- fused split-bf16 GEMM on h[t-1] (buffer p) ----
            #pragma unroll
            for (int i = 0; i < 5; i++)
                #pragma unroll
                for (int r = 0; r < 4; r++) d[i][r] = 0.0f;

            const uint32_t ah_base = aaddr[p];

            #pragma unroll
            for (int kk = 0; kk < 6; kk++) {
                const uint32_t off = (uint32_t)(kk * 32);   // 16 cols * 2B

                uint32_t ah[4], al[4];
                LDSM_X4(ah[0], ah[1], ah[2], ah[3], ah_base + off);
                LDSM_X4(al[0], al[1], al[2], al[3], ah_base + ALO * 2 + off);

                #pragma unroll
                for (int j = 0; j < 2; j++) {
                    uint32_t bh0, bh1, bh2, bh3;
                    LDSM_X4(bh0, bh1, bh2, bh3, bph[j] + off);
                    MMA16816(d[2*j],   ah[0], ah[1], ah[2], ah[3], bh0, bh1);
                    MMA16816(d[2*j],   al[0], al[1], al[2], al[3], bh0, bh1);
                    MMA16816(d[2*j+1], ah[0], ah[1], ah[2], ah[3], bh2, bh3);
                    MMA16816(d[2*j+1], al[0], al[1], al[2], al[3], bh2, bh3);
                    uint32_t bl0, bl1, bl2r, bl3;
                    LDSM_X4(bl0, bl1, bl2r, bl3, bpl[j] + off);
                    MMA16816(d[2*j],   ah[0], ah[1], ah[2], ah[3], bl0, bl1);
                    MMA16816(d[2*j+1], ah[0], ah[1], ah[2], ah[3], bl2r, bl3);
                }
                {
                    uint32_t b0, b1;
                    LDSM_X2(b0, b1, bs4h + off);
                    MMA16816(d[4], ah[0], ah[1], ah[2], ah[3], b0, b1);
                    MMA16816(d[4], al[0], al[1], al[2], al[3], b0, b1);
                    uint32_t c0, c1v;
                    LDSM_X2(c0, c1v, bs4l + off);
                    MMA16816(d[4], ah[0], ah[1], ah[2], ah[3], c0, c1v);
                }
            }
            {   // kk = 6: hi*hi only (cols 96-111; lo corrections dropped)
                const uint32_t off = 6u * 32u;
                uint32_t ah[4];
                LDSM_X4(ah[0], ah[1], ah[2], ah[3], ah_base + off);
                #pragma unroll
                for (int j = 0; j < 2; j++) {
                    uint32_t bh0, bh1, bh2, bh3;
                    LDSM_X4(bh0, bh1, bh2, bh3, bph[j] + off);
                    MMA16816(d[2*j],   ah[0], ah[1], ah[2], ah[3], bh0, bh1);
                    MMA16816(d[2*j+1], ah[0], ah[1], ah[2], ah[3], bh2, bh3);
                }
                uint32_t b0, b1;
                LDSM_X2(b0, b1, bs4h + off);
                MMA16816(d[4], ah[0], ah[1], ah[2], ah[3], b0, b1);
            }
        } else if (l2) {
            // ---- layer-2 for step t-1 (reads c1 buffer (t-1)&1) ----
            if (t > 0) {
                const int tt = t - 1;
                const float* cp = c1sh + ((t - 1) & 1) * CBUF + bl2 * CSTR;
                float di = 0.f, df = 0.f, dg = 0.f, dz = 0.f;
                #pragma unroll 10
                for (int uu = 0; uu < CELL; uu++) {
                    float cv  = cp[uu];
                    float4 w4 = *(const float4*)(w2i + uu * 4);
                    di = fmaf(cv, w4.x, di);
                    df = fmaf(cv, w4.y, df);
                    dg = fmaf(cv, w4.z, dg);
                    dz = fmaf(cv, w4.w, dz);
                }
                float pi = fmaf(h2, whh2[0], di + b2c[0]);
                float pf = fmaf(h2, whh2[1], df + b2c[1]);
                float pg = fmaf(h2, whh2[2], dg + b2c[2]);
                float po = fmaf(h2, whh2[3], dz + b2c[3]);
                float c  = sigm(pf) * c2 + sigm(pi) * tanh_f(pg);
                c2 = c;
                h2 = sigm(po) * tanh_f(c);
                if (t >= T) xsh[bl2] = c;               // x for future step t
                if (tt >= T) out[(size_t)(bglob0 + bl2) * FUT + (tt - T)] = c;
            }
        }

        // future phase needs c2[t-1] (xsh) before the epilogue
        if (fut) __syncthreads();

        if (cw) {
            if (fut) xv = xsh[rowm];
            // ---- epilogue: writes A buffer p^1 and c1 buffer p ----
            __nv_bfloat16* aw = Ash + (p ^ 1) * ABUF + rowm * ASTRIDE;
            float*         cwv = c1sh + p * CBUF + rowm * CSTR;
            #pragma unroll
            for (int i = 0; i < 5; i++) {
                const int u = 2 * (5 * g + i) + (q >> 1);
                float* dd = d[i];
                // exchange with lane^1: even keeps row r, odd keeps row r+8
                float g0 = pp ? dd[0] : dd[2];
                float g1 = pp ? dd[1] : dd[3];
                float r0 = __shfl_xor_sync(0xffffffffu, g0, 1);
                float r1 = __shfl_xor_sync(0xffffffffu, g1, 1);
                float gi, gf, gg, go;
                if (!pp) { gi = dd[0]; gf = dd[1]; gg = r0;    go = r1;    }
                else     { gi = r0;    gf = r1;    gg = dd[2]; go = dd[3]; }

                const float4 bs = *(const float4*)(bsum_sh + u * 4);
                const float4 wi = *(const float4*)(wih_sh + u * 4);
                float pi = fmaf(xv, wi.x, gi + bs.x);
                float pf = fmaf(xv, wi.y, gf + bs.y);
                float pg = fmaf(xv, wi.z, gg + bs.z);
                float po = fmaf(xv, wi.w, go + bs.w);
                float c = sigm_fast(pf) * c1r[i] + sigm_fast(pi) * tanh_hw(pg);
                c1r[i] = c;
                float h = sigm_fast(po) * tanh_hw(c);

                cwv[u] = c;
                __nv_bfloat16 hh = __float2bfloat16(h);
                aw[u] = hh;
                if (u < 96)
                    aw[ALO + u] = __float2bfloat16(h - __bfloat162float(hh));
            }
        }

        __syncthreads();   // step boundary: all buffers published
    }

    // drain: layer-2 for the final step TOT-1
    if (l2) {
        const int tt = TOT - 1;
        const float* cp = c1sh + ((TOT - 1) & 1) * CBUF + bl2 * CSTR;
        float di = 0.f, df = 0.f, dg = 0.f, dz = 0.f;
        #pragma unroll 10
        for (int uu = 0; uu < CELL; uu++) {
            float cv  = cp[uu];
            float4 w4 = *(const float4*)(w2i + uu * 4);
            di = fmaf(cv, w4.x, di);
            df = fmaf(cv, w4.y, df);
            dg = fmaf(cv, w4.z, dg);
            dz = fmaf(cv, w4.w, dz);
        }
        float pi = fmaf(h2, whh2[0], di + b2c[0]);
        float pf = fmaf(h2, whh2[1], df + b2c[1]);
        float pg = fmaf(h2, whh2[2], dg + b2c[2]);
        float po = fmaf(h2, whh2[3], dz + b2c[3]);
        float c  = sigm(pf) * c2 + sigm(pi) * tanh_f(pg);
        out[(size_t)(bglob0 + bl2) * FUT + (tt - T)] = c;
    }
}

extern "C" void kernel_launch(void* const* d_in, const int* in_sizes, int n_in,
                              void* d_out, int out_size)
{
    const float* input = (const float*)d_in[0];
    const float* W_ih1 = (const float*)d_in[1];
    const float* W_hh1 = (const float*)d_in[2];
    const float* b_ih1 = (const float*)d_in[3];
    const float* b_hh1 = (const float*)d_in[4];
    const float* W_ih2 = (const float*)d_in[5];
    const float* W_hh2 = (const float*)d_in[6];
    const float* b_ih2 = (const float*)d_in[7];
    const float* b_hh2 = (const float*)d_in[8];
    float* out = (float*)d_out;

    const int Btot = 4096;
    const int T    = in_sizes[0] / Btot;   // 512
    const int FUT  = out_size   / Btot;    // 64

    const int smem = (400 * WSTR + 400 * WLOSTR + 2 * ABUF) * 2   // bf16 regions
                   + (2 * CBUF + 400 * 3 + NB) * 4;               // fp32 regions
                   // = (44800+38400+13824)*2 + (6464+1232)*4 = 224,832 B

    cudaFuncSetAttribute(tsrnn_kernel,
                         cudaFuncAttributeMaxDynamicSharedMemorySize, smem);

    tsrnn_kernel<<<Btot / NB, THREADS, smem>>>(
        input, W_ih1, W_hh1, b_ih1, b_hh1,
        W_ih2, W_hh2, b_ih2, b_hh2,
        out, T, FUT, Btot);
}

// round 15
// speedup vs baseline: 1.0009x; 1.0008x over previous
#include <cuda_runtime.h>
#include <cuda_bf16.h>
#include <cstddef>
#include <cstdint>

// Two-layer LSTM recurrence, persistent kernel, TENSOR-CORE layer-1 GEMV.
// R13 = R12 (20 compute warps x m-split, fused split-bf16 mma.m16n8k16)
// with full double-buffering of h (Ash) and c1 so the OBSERVED phase runs
// with a SINGLE barrier per step (GEMM, layer-2, and epilogue overlap).
// Space for the second buffers comes from dropping dead padding: WSTR 112,
// and the lo-precision correction is dropped for k-cols 96..111 (4 real
// columns lose ~2^-9 relative correction -> negligible vs 1e-3 budget).
//
// 128 blocks x 672 threads:
//   warps 0-19 : compute. g = wid>>1 (n-group), mt = wid&1 (m-tile).
//   warp 20    : layer-2 (lane = batch elem), one step behind.

#define CELL     100
#define NB       32
#define THREADS  672
#define L2BASE   640
#define ASTRIDE  216      // bf16/row: hi 0-111, lo 112-207 (96 cols)
#define ALO      112
#define WSTR     112      // Whi row stride (bf16)
#define WLOSTR   96       // Wlo row stride (bf16)
#define CSTR     101      // c1 row stride (floats), [batch][unit]
#define ABUF     (32 * ASTRIDE)   // bf16 elems per A buffer
#define CBUF     (32 * CSTR)      // floats per c1 buffer

#define LDSM_X4(r0,r1,r2,r3, addr) \
  asm volatile("ldmatrix.sync.aligned.m8n8.x4.shared.b16 {%0,%1,%2,%3}, [%4];" \
    : "=r"(r0), "=r"(r1), "=r"(r2), "=r"(r3) : "r"(addr))
#define LDSM_X2(r0,r1, addr) \
  asm volatile("ldmatrix.sync.aligned.m8n8.x2.shared.b16 {%0,%1}, [%2];" \
    : "=r"(r0), "=r"(r1) : "r"(addr))
#define MMA16816(d, a0,a1,a2,a3, b0,b1) \
  asm volatile("mma.sync.aligned.m16n8k16.row.col.f32.bf16.bf16.f32 " \
    "{%0,%1,%2,%3}, {%4,%5,%6,%7}, {%8,%9}, {%0,%1,%2,%3};" \
    : "+f"((d)[0]), "+f"((d)[1]), "+f"((d)[2]), "+f"((d)[3]) \
    : "r"(a0), "r"(a1), "r"(a2), "r"(a3), "r"(b0), "r"(b1))

__device__ __forceinline__ float rcp_approx(float x) {
    float r;
    asm("rcp.approx.f32 %0, %1;" : "=f"(r) : "f"(x));
    return r;
}
// ---- fast path (compute warps): single-MUFU HW tanh ----
__device__ __forceinline__ float tanh_hw(float x) {
    float r;
    asm("tanh.approx.f32 %0, %1;" : "=f"(r) : "f"(x));
    return r;
}
__device__ __forceinline__ float sigm_fast(float x) {
    return fmaf(0.5f, tanh_hw(0.5f * x), 0.5f);
}
// ---- exact path (layer-2 warp) ----
__device__ __forceinline__ float sigm(float x) {
    return rcp_approx(1.0f + __expf(-x));
}
__device__ __forceinline__ float tanh_f(float x) {
    float e = __expf(2.0f * x);
    return fmaf(-2.0f, rcp_approx(e + 1.0f), 1.0f);
}
__device__ __forceinline__ uint32_t smem_u32(const void* p) {
    return (uint32_t)__cvta_generic_to_shared(p);
}

__global__ void __launch_bounds__(THREADS, 1)
tsrnn_kernel(const float* __restrict__ input,
             const float* __restrict__ W_ih1, const float* __restrict__ W_hh1,
             const float* __restrict__ b_ih1, const float* __restrict__ b_hh1,
             const float* __restrict__ W_ih2, const float* __restrict__ W_hh2,
             const float* __restrict__ b_ih2, const float* __restrict__ b_hh2,
             float* __restrict__ out, int T, int FUT, int Btot)
{
    extern __shared__ char smem[];
    __nv_bfloat16* Whi = (__nv_bfloat16*)smem;          // [400][112]  row n = 4u+k
    __nv_bfloat16* Wlo = Whi + 400 * WSTR;              // [400][96]
    __nv_bfloat16* Ash = Wlo + 400 * WLOSTR;            // [2][32][216]
    float* c1sh   = (float*)(Ash + 2 * ABUF);           // [2][32][101]
    float* w2i    = c1sh + 2 * CBUF;                    // [100][4]
    float* wih_sh = w2i + 400;                          // [100][4]
    float* bsum_sh= wih_sh + 400;                       // [100][4]
    float* xsh    = bsum_sh + 400;                      // [32] (future phase)

    const int tid    = threadIdx.x;
    const int bglob0 = blockIdx.x * NB;
    const int wid    = tid >> 5;
    const int lane   = tid & 31;

    // ================= staging =================
    for (int idx = tid; idx < 400 * WSTR; idx += THREADS) {
        int n = idx / WSTR, kk = idx - n * WSTR;
        int u = n >> 2, k = n & 3;
        float w = (kk < CELL) ? W_hh1[(k * CELL + u) * CELL + kk] : 0.0f;
        Whi[idx] = __float2bfloat16(w);
    }
    for (int idx = tid; idx < 400 * WLOSTR; idx += THREADS) {
        int n = idx / WLOSTR, kk = idx - n * WLOSTR;   // kk < 96 < 100
        int u = n >> 2, k = n & 3;
        float w = W_hh1[(k * CELL + u) * CELL + kk];
        Wlo[idx] = __float2bfloat16(w - __bfloat162float(__float2bfloat16(w)));
    }
    for (int idx = tid; idx < 2 * ABUF; idx += THREADS)
        Ash[idx] = __float2bfloat16(0.0f);
    for (int idx = tid; idx < 2 * CBUF; idx += THREADS) c1sh[idx] = 0.0f;
    for (int idx = tid; idx < 400; idx += THREADS) {
        int u = idx >> 2, k = idx & 3;
        w2i[idx]    = W_ih2[k * CELL + u];
        wih_sh[idx] = W_ih1[k * CELL + u];
        bsum_sh[idx]= b_ih1[k * CELL + u] + b_hh1[k * CELL + u];
    }
    if (tid < NB) xsh[tid] = 0.0f;

    // ================= per-thread setup =================
    const bool cw = (wid < 20);                 // compute warp
    const bool l2 = (tid >= L2BASE);            // warp 20
    const int  g  = wid >> 1;                   // n-group (0..9)
    const int  mt = wid & 1;                    // m-tile (0..1)
    const int  q  = lane & 3;
    const int  pp = q & 1;                      // 0: holds (i,f); 1: holds (g,o)
    const int  rowbase = lane >> 2;
    const int  rowm = mt * 16 + rowbase + (pp ? 8 : 0);  // this thread's batch row

    // ldmatrix lane addresses (byte offsets precomputed)
    const uint32_t Au32  = smem_u32(Ash);
    const uint32_t Whi32 = smem_u32(Whi);
    const uint32_t Wlo32 = smem_u32(Wlo);
    uint32_t aaddr[2], bph[2], bpl[2], bs4h = 0, bs4l = 0;
    if (cw) {
        // A: 16 rows of own m-tile, both k-halves, per buffer
        const uint32_t arow = ((mt * 16 + (lane & 15)) * ASTRIDE + (lane >> 4) * 8) * 2;
        aaddr[0] = Au32 + arow;
        aaddr[1] = Au32 + ABUF * 2 + arow;
        // B pairs: x4 loads n-tiles (5g+2j, 5g+2j+1), both k-halves
        const int sub = lane >> 3, l8 = lane & 7;
        const int ntoff = sub >> 1, khalf = sub & 1;
        #pragma unroll
        for (int j = 0; j < 2; j++) {
            int nt = 5 * g + 2 * j + ntoff;
            bph[j] = Whi32 + ((8 * nt + l8) * WSTR   + khalf * 8) * 2;
            bpl[j] = Wlo32 + ((8 * nt + l8) * WLOSTR + khalf * 8) * 2;
        }
        // B single: n-tile 5g+4 (x2: lanes 0-15, two k-halves)
        const int l4 = lane & 15;
        bs4h = Whi32 + ((8 * (5 * g + 4) + (l4 & 7)) * WSTR   + ((l4 >> 3) & 1) * 8) * 2;
        bs4l = Wlo32 + ((8 * (5 * g + 4) + (l4 & 7)) * WLOSTR + ((l4 >> 3) & 1) * 8) * 2;
    }

    // layer-2 per-lane constants + state
    const int bl2 = tid - L2BASE;
    float whh2[4], b2c[4];
    float h2 = 0.0f, c2 = 0.0f;
    if (l2) {
        #pragma unroll
        for (int k = 0; k < 4; k++) {
            whh2[k] = W_hh2[k];
            b2c[k]  = b_ih2[k] + b_hh2[k];
        }
    }

    float c1r[5];
    #pragma unroll
    for (int i = 0; i < 5; i++) c1r[i] = 0.0f;

    __syncthreads();

    // ================= main loop =================
    const int TOT = T + FUT;
    for (int t = 0; t < TOT; ++t) {
        const bool fut = (t >= T);
        const int p = t & 1;          // A buffer holding h[t-1]; c1[t] -> buf p
        float d[5][4];
        float xv = 0.0f;

        if (cw) {
            // ---- x prefetch (observed): LDG issued before the GEMM ----
            if (!fut) {
                xv = __ldg(input + (size_t)t * Btot + bglob0 + rowm);
            }

            // ---- fused split-bf16 GEMM on h[t-1] (buffer p) ----
            #pragma unroll
            for (int i = 0; i < 5; i++)
                #pragma unroll
                for (int r = 0; r < 4; r++) d[i][r] = 0.0f;

            const uint32_t ah_base = aaddr[p];

            #pragma unroll
            for (int kk = 0; kk < 6; kk++) {
                const uint32_t off = (uint32_t)(kk * 32);   // 16 cols * 2B

                uint32_t ah[4], al[4];
                LDSM_X4(ah[0], ah[1], ah[2], ah[3], ah_base + off);
                LDSM_X4(al[0], al[1], al[2], al[3], ah_base + ALO * 2 + off);

                #pragma unroll
                for (int j = 0; j < 2; j++) {
                    uint32_t bh0, bh1, bh2, bh3;
                    LDSM_X4(bh0, bh1, bh2, bh3, bph[j] + off);
                    MMA16816(d[2*j],   ah[0], ah[1], ah[2], ah[3], bh0, bh1);
                    MMA16816(d[2*j],   al[0], al[1], al[2], al[3], bh0, bh1);
                    MMA16816(d[2*j+1], ah[0], ah[1], ah[2], ah[3], bh2, bh3);
                    MMA16816(d[2*j+1], al[0], al[1], al[2], al[3], bh2, bh3);
                    uint32_t bl0, bl1, bl2r, bl3;
                    LDSM_X4(bl0, bl1, bl2r, bl3, bpl[j] + off);
                    MMA16816(d[2*j],   ah[0], ah[1], ah[2], ah[3], bl0, bl1);
                    MMA16816(d[2*j+1], ah[0], ah[1], ah[2], ah[3], bl2r, bl3);
                }
                {
                    uint32_t b0, b1;
                    LDSM_X2(b0, b1, bs4h + off);
                    MMA16816(d[4], ah[0], ah[1], ah[2], ah[3], b0, b1);
                    MMA16816(d[4], al[0], al[1], al[2], al[3], b0, b1);
                    uint32_t c0, c1v;
                    LDSM_X2(c0, c1v, bs4l + off);
                    MMA16816(d[4], ah[0], ah[1], ah[2], ah[3], c0, c1v);
                }
            }
            {   // kk = 6: hi*hi only (cols 96-111; lo corrections dropped)
                const uint32_t off = 6u * 32u;
                uint32_t ah[4];
                LDSM_X4(ah[0], ah[1], ah[2], ah[3], ah_base + off);
                #pragma unroll
                for (int j = 0; j < 2; j++) {
                    uint32_t bh0, bh1, bh2, bh3;
                    LDSM_X4(bh0, bh1, bh2, bh3, bph[j] + off);
                    MMA16816(d[2*j],   ah[0], ah[1], ah[2], ah[3], bh0, bh1);
                    MMA16816(d[2*j+1], ah[0], ah[1], ah[2], ah[3], bh2, bh3);
                }
                uint32_t b0, b1;
                LDSM_X2(b0, b1, bs4h + off);
                MMA16816(d[4], ah[0], ah[1], ah[2], ah[3], b0, b1);
            }
        } else if (l2) {
            // ---- layer-2 for step t-1 (reads c1 buffer (t-1)&1) ----
            if (t > 0) {
                const int tt = t - 1;
                const float* cp = c1sh + ((t - 1) & 1) * CBUF + bl2 * CSTR;
                float di = 0.f, df = 0.f, dg = 0.f, dz = 0.f;
                #pragma unroll 10
                for (int uu = 0; uu < CELL; uu++) {
                    float cv  = cp[uu];
                    float4 w4 = *(const float4*)(w2i + uu * 4);
                    di = fmaf(cv, w4.x, di);
                    df = fmaf(cv, w4.y, df);
                    dg = fmaf(cv, w4.z, dg);
                    dz = fmaf(cv, w4.w, dz);
                }
                float pi = fmaf(h2, whh2[0], di + b2c[0]);
                float pf = fmaf(h2, whh2[1], df + b2c[1]);
                float pg = fmaf(h2, whh2[2], dg + b2c[2]);
                float po = fmaf(h2, whh2[3], dz + b2c[3]);
                float c  = sigm(pf) * c2 + sigm(pi) * tanh_f(pg);
                c2 = c;
                h2 = sigm(po) * tanh_f(c);
                if (t >= T) xsh[bl2] = c;               // x for future step t
                if (tt >= T) out[(size_t)(bglob0 + bl2) * FUT + (tt - T)] = c;
            }
        }

        // future phase needs c2[t-1] (xsh) before the epilogue
        if (fut) __syncthreads();

        if (cw) {
            if (fut) xv = xsh[rowm];
            // ---- epilogue: writes A buffer p^1 and c1 buffer p ----
            __nv_bfloat16* aw = Ash + (p ^ 1) * ABUF + rowm * ASTRIDE;
            float*         cwv = c1sh + p * CBUF + rowm * CSTR;
            #pragma unroll
            for (int i = 0; i < 5; i++) {
                const int u = 2 * (5 * g + i) + (q >> 1);
                float* dd = d[i];
                // exchange with lane^1: even keeps row r, odd keeps row r+8
                float g0 = pp ? dd[0] : dd[2];
                float g1 = pp ? dd[1] : dd[3];
                float r0 = __shfl_xor_sync(0xffffffffu, g0, 1);
                float r1 = __shfl_xor_sync(0xffffffffu, g1, 1);
                float gi, gf, gg, go;
                if (!pp) { gi = dd[0]; gf = dd[1]; gg = r0;    go = r1;    }
                else     { gi = r0;    gf = r1;    gg = dd[2]; go = dd[3]; }

                const float4 bs = *(const float4*)(bsum_sh + u * 4);
                const float4 wi = *(const float4*)(wih_sh + u * 4);
                float pi = fmaf(xv, wi.x, gi + bs.x);
                float pf = fmaf(xv, wi.y, gf + bs.y);
                float pg = fmaf(xv, wi.z, gg + bs.z);
                float po = fmaf(xv, wi.w, go + bs.w);
                float c = sigm_fast(pf) * c1r[i] + sigm_fast(pi) * tanh_hw(pg);
                c1r[i] = c;
                float h = sigm_fast(po) * tanh_hw(c);

                cwv[u] = c;
                __nv_bfloat16 hh = __float2bfloat16(h);
                aw[u] = hh;
                if (u < 96)
                    aw[ALO + u] = __float2bfloat16(h - __bfloat162float(hh));
            }
        }

        __syncthreads();   // step boundary: all buffers published
    }

    // drain: layer-2 for the final step TOT-1
    if (l2) {
        const int tt = TOT - 1;
        const float* cp = c1sh + ((TOT - 1) & 1) * CBUF + bl2 * CSTR;
        float di = 0.f, df = 0.f, dg = 0.f, dz = 0.f;
        #pragma unroll 10
        for (int uu = 0; uu < CELL; uu++) {
            float cv  = cp[uu];
            float4 w4 = *(const float4*)(w2i + uu * 4);
            di = fmaf(cv, w4.x, di);
            df = fmaf(cv, w4.y, df);
            dg = fmaf(cv, w4.z, dg);
            dz = fmaf(cv, w4.w, dz);
        }
        float pi = fmaf(h2, whh2[0], di + b2c[0]);
        float pf = fmaf(h2, whh2[1], df + b2c[1]);
        float pg = fmaf(h2, whh2[2], dg + b2c[2]);
        float po = fmaf(h2, whh2[3], dz + b2c[3]);
        float c  = sigm(pf) * c2 + sigm(pi) * tanh_f(pg);
        out[(size_t)(bglob0 + bl2) * FUT + (tt - T)] = c;
    }
}

extern "C" void kernel_launch(void* const* d_in, const int* in_sizes, int n_in,
                              void* d_out, int out_size)
{
    const float* input = (const float*)d_in[0];
    const float* W_ih1 = (const float*)d_in[1];
    const float* W_hh1 = (const float*)d_in[2];
    const float* b_ih1 = (const float*)d_in[3];
    const float* b_hh1 = (const float*)d_in[4];
    const float* W_ih2 = (const float*)d_in[5];
    const float* W_hh2 = (const float*)d_in[6];
    const float* b_ih2 = (const float*)d_in[7];
    const float* b_hh2 = (const float*)d_in[8];
    float* out = (float*)d_out;

    const int Btot = 4096;
    const int T    = in_sizes[0] / Btot;   // 512
    const int FUT  = out_size   / Btot;    // 64

    const int smem = (400 * WSTR + 400 * WLOSTR + 2 * ABUF) * 2   // bf16 regions
                   + (2 * CBUF + 400 * 3 + NB) * 4;               // fp32 regions
                   // = (44800+38400+13824)*2 + (6464+1232)*4 = 224,832 B

    cudaFuncSetAttribute(tsrnn_kernel,
                         cudaFuncAttributeMaxDynamicSharedMemorySize, smem);

    tsrnn_kernel<<<Btot / NB, THREADS, smem>>>(
        input, W_ih1, W_hh1, b_ih1, b_hh1,
        W_ih2, W_hh2, b_ih2, b_hh2,
        out, T, FUT, Btot);
}

// round 16
// speedup vs baseline: 1.6175x; 1.6159x over previous
#include <cuda_runtime.h>
#include <cuda_bf16.h>
#include <cstddef>
#include <cstdint>

// Two-layer LSTM recurrence, persistent kernel, TENSOR-CORE layer-1 GEMV.
// R16 = R12 (best: fused split-bf16 mma.m16n8k16, 20 compute warps m-split)
//  + Ash double-buffered (GEMM reads buf p, epilogue writes buf p^1)
//  + pairwise mid-step barriers: compute pair {2g,2g+1} bar.sync(1+g,96),
//    layer-2 warp bar.arrive on all 10 -> no global mid-step convoy.
// Full split precision kept. All ldmatrix row strides ODD in 16B quads
// (A 29, Whi 15, Wlo 13) -> conflict-free (R13's regression was even-quad
// strides: 4-way LDSM bank conflicts).
//
// 128 blocks x 672 threads:
//   warps 0-19 : compute. g = wid>>1 (n-group), mt = wid&1 (m-tile).
//   warp 20    : layer-2 (lane = batch elem), one step behind.

#define CELL     100
#define NB       32
#define THREADS  672
#define L2BASE   640
#define ASTRIDE  232      // bf16/row: hi 0-111, pad, lo 120-231  (29 quads, odd)
#define ALO      120
#define WSTR     120      // Whi row stride (15 quads, odd)
#define WLOSTR   104      // Wlo row stride (13 quads, odd); cols 100-103 zero
#define CSTRIDE  33       // c1sh row stride (floats)
#define ABUF     (32 * ASTRIDE)   // bf16 elems per A buffer

#define LDSM_X4(r0,r1,r2,r3, addr) \
  asm volatile("ldmatrix.sync.aligned.m8n8.x4.shared.b16 {%0,%1,%2,%3}, [%4];" \
    : "=r"(r0), "=r"(r1), "=r"(r2), "=r"(r3) : "r"(addr))
#define LDSM_X2(r0,r1, addr) \
  asm volatile("ldmatrix.sync.aligned.m8n8.x2.shared.b16 {%0,%1}, [%2];" \
    : "=r"(r0), "=r"(r1) : "r"(addr))
#define MMA16816(d, a0,a1,a2,a3, b0,b1) \
  asm volatile("mma.sync.aligned.m16n8k16.row.col.f32.bf16.bf16.f32 " \
    "{%0,%1,%2,%3}, {%4,%5,%6,%7}, {%8,%9}, {%0,%1,%2,%3};" \
    : "+f"((d)[0]), "+f"((d)[1]), "+f"((d)[2]), "+f"((d)[3]) \
    : "r"(a0), "r"(a1), "r"(a2), "r"(a3), "r"(b0), "r"(b1))

__device__ __forceinline__ float rcp_approx(float x) {
    float r;
    asm("rcp.approx.f32 %0, %1;" : "=f"(r) : "f"(x));
    return r;
}
// ---- fast path (compute warps): single-MUFU HW tanh ----
__device__ __forceinline__ float tanh_hw(float x) {
    float r;
    asm("tanh.approx.f32 %0, %1;" : "=f"(r) : "f"(x));
    return r;
}
__device__ __forceinline__ float sigm_fast(float x) {
    return fmaf(0.5f, tanh_hw(0.5f * x), 0.5f);
}
// ---- exact path (layer-2 warp) ----
__device__ __forceinline__ float sigm(float x) {
    return rcp_approx(1.0f + __expf(-x));
}
__device__ __forceinline__ float tanh_f(float x) {
    float e = __expf(2.0f * x);
    return fmaf(-2.0f, rcp_approx(e + 1.0f), 1.0f);
}
__device__ __forceinline__ uint32_t smem_u32(const void* p) {
    return (uint32_t)__cvta_generic_to_shared(p);
}

__global__ void __launch_bounds__(THREADS, 1)
tsrnn_kernel(const float* __restrict__ input,
             const float* __restrict__ W_ih1, const float* __restrict__ W_hh1,
             const float* __restrict__ b_ih1, const float* __restrict__ b_hh1,
             const float* __restrict__ W_ih2, const float* __restrict__ W_hh2,
             const float* __restrict__ b_ih2, const float* __restrict__ b_hh2,
             float* __restrict__ out, int T, int FUT, int Btot)
{
    extern __shared__ char smem[];
    __nv_bfloat16* Whi = (__nv_bfloat16*)smem;          // [400][120]  row n = 4u+k
    __nv_bfloat16* Wlo = Whi + 400 * WSTR;              // [400][104]
    __nv_bfloat16* Ash = Wlo + 400 * WLOSTR;            // [2][32][232]
    float* c1sh   = (float*)(Ash + 2 * ABUF);           // [100][33]
    float* w2i    = c1sh + CELL * CSTRIDE;              // [100][4]
    float* wih_sh = w2i + 400;                          // [100][4]
    float* bsum_sh= wih_sh + 400;                       // [100][4]
    float* xsh    = bsum_sh + 400;                      // [32] (future phase)

    const int tid    = threadIdx.x;
    const int bglob0 = blockIdx.x * NB;
    const int wid    = tid >> 5;
    const int lane   = tid & 31;

    // ================= staging =================
    for (int idx = tid; idx < 400 * WSTR; idx += THREADS) {
        int n = idx / WSTR, kk = idx - n * WSTR;
        int u = n >> 2, k = n & 3;
        float w = (kk < CELL) ? W_hh1[(k * CELL + u) * CELL + kk] : 0.0f;
        Whi[idx] = __float2bfloat16(w);
    }
    for (int idx = tid; idx < 400 * WLOSTR; idx += THREADS) {
        int n = idx / WLOSTR, kk = idx - n * WLOSTR;
        int u = n >> 2, k = n & 3;
        float lo = 0.0f;
        if (kk < CELL) {
            float w = W_hh1[(k * CELL + u) * CELL + kk];
            lo = w - __bfloat162float(__float2bfloat16(w));
        }
        Wlo[idx] = __float2bfloat16(lo);
    }
    for (int idx = tid; idx < 2 * ABUF; idx += THREADS)
        Ash[idx] = __float2bfloat16(0.0f);
    for (int idx = tid; idx < CELL * CSTRIDE; idx += THREADS) c1sh[idx] = 0.0f;
    for (int idx = tid; idx < 400; idx += THREADS) {
        int u = idx >> 2, k = idx & 3;
        w2i[idx]    = W_ih2[k * CELL + u];
        wih_sh[idx] = W_ih1[k * CELL + u];
        bsum_sh[idx]= b_ih1[k * CELL + u] + b_hh1[k * CELL + u];
    }
    if (tid < NB) xsh[tid] = 0.0f;

    // ================= per-thread setup =================
    const bool cw = (wid < 20);                 // compute warp
    const bool l2 = (tid >= L2BASE);            // warp 20
    const int  g  = wid >> 1;                   // n-group (0..9)
    const int  mt = wid & 1;                    // m-tile (0..1)
    const int  q  = lane & 3;
    const int  pp = q & 1;                      // 0: holds (i,f); 1: holds (g,o)
    const int  rowbase = lane >> 2;
    const int  rowm = mt * 16 + rowbase + (pp ? 8 : 0);  // this thread's batch row

    // ldmatrix lane addresses (byte offsets precomputed)
    const uint32_t Au32  = smem_u32(Ash);
    const uint32_t Whi32 = smem_u32(Whi);
    const uint32_t Wlo32 = smem_u32(Wlo);
    uint32_t aaddr[2], bph[2], bpl[2], bs4h = 0, bs4l = 0;
    if (cw) {
        // A: 16 rows of own m-tile, both k-halves, per buffer
        const uint32_t arow = ((mt * 16 + (lane & 15)) * ASTRIDE + (lane >> 4) * 8) * 2;
        aaddr[0] = Au32 + arow;
        aaddr[1] = Au32 + ABUF * 2 + arow;
        // B pairs: x4 loads n-tiles (5g+2j, 5g+2j+1), both k-halves
        const int sub = lane >> 3, l8 = lane & 7;
        const int ntoff = sub >> 1, khalf = sub & 1;
        #pragma unroll
        for (int j = 0; j < 2; j++) {
            int nt = 5 * g + 2 * j + ntoff;
            bph[j] = Whi32 + ((8 * nt + l8) * WSTR   + khalf * 8) * 2;
            bpl[j] = Wlo32 + ((8 * nt + l8) * WLOSTR + khalf * 8) * 2;
        }
        // B single: n-tile 5g+4 (x2: lanes 0-15, two k-halves)
        const int l4 = lane & 15;
        bs4h = Whi32 + ((8 * (5 * g + 4) + (l4 & 7)) * WSTR   + ((l4 >> 3) & 1) * 8) * 2;
        bs4l = Wlo32 + ((8 * (5 * g + 4) + (l4 & 7)) * WLOSTR + ((l4 >> 3) & 1) * 8) * 2;
    }

    // layer-2 per-lane constants + state
    const int bl2 = tid - L2BASE;
    float whh2[4], b2c[4];
    float h2 = 0.0f, c2 = 0.0f;
    if (l2) {
        #pragma unroll
        for (int k = 0; k < 4; k++) {
            whh2[k] = W_hh2[k];
            b2c[k]  = b_ih2[k] + b_hh2[k];
        }
    }

    float c1r[5];
    #pragma unroll
    for (int i = 0; i < 5; i++) c1r[i] = 0.0f;

    __syncthreads();

    // ================= main loop =================
    const int TOT = T + FUT;
    for (int t = 0; t < TOT; ++t) {
        const bool fut = (t >= T);
        const int p = t & 1;          // A buffer holding h[t-1]
        float d[5][4];
        float xv = 0.0f;

        if (cw) {
            // ---- x prefetch (observed): LDG issued before the GEMM ----
            if (!fut) {
                xv = __ldg(input + (size_t)t * Btot + bglob0 + rowm);
            }

            // ---- fused split-bf16 GEMM on h[t-1] (A buffer p) ----
            #pragma unroll
            for (int i = 0; i < 5; i++)
                #pragma unroll
                for (int r = 0; r < 4; r++) d[i][r] = 0.0f;

            const uint32_t ah_base = aaddr[p];

            #pragma unroll
            for (int kk = 0; kk < 7; kk++) {
                const uint32_t off = (uint32_t)(kk * 32);   // 16 cols * 2B

                uint32_t ah[4], al[4];
                LDSM_X4(ah[0], ah[1], ah[2], ah[3], ah_base + off);
                LDSM_X4(al[0], al[1], al[2], al[3], ah_base + ALO * 2 + off);

                #pragma unroll
                for (int j = 0; j < 2; j++) {
                    uint32_t bh0, bh1, bh2, bh3;
                    LDSM_X4(bh0, bh1, bh2, bh3, bph[j] + off);
                    MMA16816(d[2*j],   ah[0], ah[1], ah[2], ah[3], bh0, bh1);
                    MMA16816(d[2*j],   al[0], al[1], al[2], al[3], bh0, bh1);
                    MMA16816(d[2*j+1], ah[0], ah[1], ah[2], ah[3], bh2, bh3);
                    MMA16816(d[2*j+1], al[0], al[1], al[2], al[3], bh2, bh3);
                    uint32_t bl0, bl1, bl2r, bl3;
                    LDSM_X4(bl0, bl1, bl2r, bl3, bpl[j] + off);
                    MMA16816(d[2*j],   ah[0], ah[1], ah[2], ah[3], bl0, bl1);
                    MMA16816(d[2*j+1], ah[0], ah[1], ah[2], ah[3], bl2r, bl3);
                }
                {
                    uint32_t b0, b1;
                    LDSM_X2(b0, b1, bs4h + off);
                    MMA16816(d[4], ah[0], ah[1], ah[2], ah[3], b0, b1);
                    MMA16816(d[4], al[0], al[1], al[2], al[3], b0, b1);
                    uint32_t c0, c1v;
                    LDSM_X2(c0, c1v, bs4l + off);
                    MMA16816(d[4], ah[0], ah[1], ah[2], ah[3], c0, c1v);
                }
            }
        } else if (l2) {
            // ---- layer-2 for step t-1 (reads c1 written last step) ----
            if (t > 0) {
                const int tt = t - 1;
                const float* cp = c1sh + bl2;
                float di = 0.f, df = 0.f, dg = 0.f, dz = 0.f;
                #pragma unroll 10
                for (int uu = 0; uu < CELL; uu++) {
                    float cv  = cp[uu * CSTRIDE];
                    float4 w4 = *(const float4*)(w2i + uu * 4);
                    di = fmaf(cv, w4.x, di);
                    df = fmaf(cv, w4.y, df);
                    dg = fmaf(cv, w4.z, dg);
                    dz = fmaf(cv, w4.w, dz);
                }
                float pi = fmaf(h2, whh2[0], di + b2c[0]);
                float pf = fmaf(h2, whh2[1], df + b2c[1]);
                float pg = fmaf(h2, whh2[2], dg + b2c[2]);
                float po = fmaf(h2, whh2[3], dz + b2c[3]);
                float c  = sigm(pf) * c2 + sigm(pi) * tanh_f(pg);
                c2 = c;
                h2 = sigm(po) * tanh_f(c);
                if (t >= T) xsh[bl2] = c;               // x for future step t
                if (tt >= T) out[(size_t)(bglob0 + bl2) * FUT + (tt - T)] = c;
            }
        }

        // ---- mid-step: pairwise barriers ----
        // compute pair {2g, 2g+1} + l2 arrival (c1 reads + xsh done) = 96
        if (cw) {
            asm volatile("bar.sync %0, 96;" :: "r"(1 + g) : "memory");
        } else if (l2) {
            #pragma unroll
            for (int b = 1; b <= 10; b++)
                asm volatile("bar.arrive %0, 96;" :: "r"(b) : "memory");
        }

        if (cw) {
            if (fut) xv = xsh[rowm];
            // ---- epilogue: writes A buffer p^1 and c1 ----
            __nv_bfloat16* aw = Ash + (p ^ 1) * ABUF + rowm * ASTRIDE;
            #pragma unroll
            for (int i = 0; i < 5; i++) {
                const int u = 2 * (5 * g + i) + (q >> 1);
                float* dd = d[i];
                // exchange with lane^1: even keeps row r, odd keeps row r+8
                float g0 = pp ? dd[0] : dd[2];
                float g1 = pp ? dd[1] : dd[3];
                float r0 = __shfl_xor_sync(0xffffffffu, g0, 1);
                float r1 = __shfl_xor_sync(0xffffffffu, g1, 1);
                float gi, gf, gg, go;
                if (!pp) { gi = dd[0]; gf = dd[1]; gg = r0;    go = r1;    }
                else     { gi = r0;    gf = r1;    gg = dd[2]; go = dd[3]; }

                const float4 bs = *(const float4*)(bsum_sh + u * 4);
                const float4 wi = *(const float4*)(wih_sh + u * 4);
                float pi = fmaf(xv, wi.x, gi + bs.x);
                float pf = fmaf(xv, wi.y, gf + bs.y);
                float pg = fmaf(xv, wi.z, gg + bs.z);
                float po = fmaf(xv, wi.w, go + bs.w);
                float c = sigm_fast(pf) * c1r[i] + sigm_fast(pi) * tanh_hw(pg);
                c1r[i] = c;
                float h = sigm_fast(po) * tanh_hw(c);

                c1sh[u * CSTRIDE + rowm] = c;
                __nv_bfloat16 hh = __float2bfloat16(h);
                aw[u] = hh;
                aw[ALO + u] = __float2bfloat16(h - __bfloat162float(hh));
            }
        }

        __syncthreads();   // step boundary: A[p^1], c1, out all published
    }

    // drain: layer-2 for the final step TOT-1
    if (l2) {
        const int tt = TOT - 1;
        const float* cp = c1sh + bl2;
        float di = 0.f, df = 0.f, dg = 0.f, dz = 0.f;
        #pragma unroll 10
        for (int uu = 0; uu < CELL; uu++) {
            float cv  = cp[uu * CSTRIDE];
            float4 w4 = *(const float4*)(w2i + uu * 4);
            di = fmaf(cv, w4.x, di);
            df = fmaf(cv, w4.y, df);
            dg = fmaf(cv, w4.z, dg);
            dz = fmaf(cv, w4.w, dz);
        }
        float pi = fmaf(h2, whh2[0], di + b2c[0]);
        float pf = fmaf(h2, whh2[1], df + b2c[1]);
        float pg = fmaf(h2, whh2[2], dg + b2c[2]);
        float po = fmaf(h2, whh2[3], dz + b2c[3]);
        float c  = sigm(pf) * c2 + sigm(pi) * tanh_f(pg);
        out[(size_t)(bglob0 + bl2) * FUT + (tt - T)] = c;
    }
}

extern "C" void kernel_launch(void* const* d_in, const int* in_sizes, int n_in,
                              void* d_out, int out_size)
{
    const float* input = (const float*)d_in[0];
    const float* W_ih1 = (const float*)d_in[1];
    const float* W_hh1 = (const float*)d_in[2];
    const float* b_ih1 = (const float*)d_in[3];
    const float* b_hh1 = (const float*)d_in[4];
    const float* W_ih2 = (const float*)d_in[5];
    const float* W_hh2 = (const float*)d_in[6];
    const float* b_ih2 = (const float*)d_in[7];
    const float* b_hh2 = (const float*)d_in[8];
    float* out = (float*)d_out;

    const int Btot = 4096;
    const int T    = in_sizes[0] / Btot;   // 512
    const int FUT  = out_size   / Btot;    // 64

    const int smem = (400 * WSTR + 400 * WLOSTR + 2 * ABUF) * 2  // bf16 regions
                   + (CELL * CSTRIDE + 400 * 3 + NB) * 4;        // fp32 regions
                   // = (48000+41600+14848)*2 + (3300+1200+32)*4 = 227,024 B

    cudaFuncSetAttribute(tsrnn_kernel,
                         cudaFuncAttributeMaxDynamicSharedMemorySize, smem);

    tsrnn_kernel<<<Btot / NB, THREADS, smem>>>(
        input, W_ih1, W_hh1, b_ih1, b_hh1,
        W_ih2, W_hh2, b_ih2, b_hh2,
        out, T, FUT, Btot);
}

// round 17
// speedup vs baseline: 1.6464x; 1.0179x over previous
#include <cuda_runtime.h>
#include <cuda_bf16.h>
#include <cstddef>
#include <cstdint>

// Two-layer LSTM recurrence, persistent kernel, TENSOR-CORE layer-1 GEMV.
// R17 = R16 split into TWO independent batch-half pipelines (rows 0-15 /
// 16-31) with enforced anti-phase GEMM alternation:
//   group 0: comp warps 0-9  + l2 warp 20, barriers {1 mid, 2 end}
//   group 1: comp warps 10-19 + l2 warp 21, barriers {3 mid, 4 end}
//   bar 5: G0-GEMM(t) done -> G1 may GEMM(t)
//   bar 6: G1-GEMM(t) done -> G0 may GEMM(t+1)
// Each group's MUFU/FFMA epilogue overlaps the other group's LDSM/HMMA
// GEMM window. Math identical to R16 (full split-bf16, fp32 pointwise).
//
// 128 blocks x 704 threads.

#define CELL     100
#define NB       32
#define THREADS  704
#define L2BASE   640
#define ASTRIDE  232      // bf16/row: hi 0-111, pad, lo 120-231  (29 quads, odd)
#define ALO      120
#define WSTR     120      // Whi row stride (15 quads, odd)
#define WLOSTR   104      // Wlo row stride (13 quads, odd); cols 100-103 zero
#define CSTRIDE  33       // c1sh row stride (floats)
#define ABUF     (32 * ASTRIDE)   // bf16 elems per A buffer

#define LDSM_X4(r0,r1,r2,r3, addr) \
  asm volatile("ldmatrix.sync.aligned.m8n8.x4.shared.b16 {%0,%1,%2,%3}, [%4];" \
    : "=r"(r0), "=r"(r1), "=r"(r2), "=r"(r3) : "r"(addr))
#define LDSM_X2(r0,r1, addr) \
  asm volatile("ldmatrix.sync.aligned.m8n8.x2.shared.b16 {%0,%1}, [%2];" \
    : "=r"(r0), "=r"(r1) : "r"(addr))
#define MMA16816(d, a0,a1,a2,a3, b0,b1) \
  asm volatile("mma.sync.aligned.m16n8k16.row.col.f32.bf16.bf16.f32 " \
    "{%0,%1,%2,%3}, {%4,%5,%6,%7}, {%8,%9}, {%0,%1,%2,%3};" \
    : "+f"((d)[0]), "+f"((d)[1]), "+f"((d)[2]), "+f"((d)[3]) \
    : "r"(a0), "r"(a1), "r"(a2), "r"(a3), "r"(b0), "r"(b1))
#define BARSYNC(id, cnt) \
  asm volatile("bar.sync %0, %1;" :: "r"(id), "r"(cnt) : "memory")
#define BARARRIVE(id, cnt) \
  asm volatile("bar.arrive %0, %1;" :: "r"(id), "r"(cnt) : "memory")

__device__ __forceinline__ float rcp_approx(float x) {
    float r;
    asm("rcp.approx.f32 %0, %1;" : "=f"(r) : "f"(x));
    return r;
}
// ---- fast path (compute warps): single-MUFU HW tanh ----
__device__ __forceinline__ float tanh_hw(float x) {
    float r;
    asm("tanh.approx.f32 %0, %1;" : "=f"(r) : "f"(x));
    return r;
}
__device__ __forceinline__ float sigm_fast(float x) {
    return fmaf(0.5f, tanh_hw(0.5f * x), 0.5f);
}
// ---- exact path (layer-2 warps) ----
__device__ __forceinline__ float sigm(float x) {
    return rcp_approx(1.0f + __expf(-x));
}
__device__ __forceinline__ float tanh_f(float x) {
    float e = __expf(2.0f * x);
    return fmaf(-2.0f, rcp_approx(e + 1.0f), 1.0f);
}
__device__ __forceinline__ uint32_t smem_u32(const void* p) {
    return (uint32_t)__cvta_generic_to_shared(p);
}

__global__ void __launch_bounds__(THREADS, 1)
tsrnn_kernel(const float* __restrict__ input,
             const float* __restrict__ W_ih1, const float* __restrict__ W_hh1,
             const float* __restrict__ b_ih1, const float* __restrict__ b_hh1,
             const float* __restrict__ W_ih2, const float* __restrict__ W_hh2,
             const float* __restrict__ b_ih2, const float* __restrict__ b_hh2,
             float* __restrict__ out, int T, int FUT, int Btot)
{
    extern __shared__ char smem[];
    __nv_bfloat16* Whi = (__nv_bfloat16*)smem;          // [400][120]  row n = 4u+k
    __nv_bfloat16* Wlo = Whi + 400 * WSTR;              // [400][104]
    __nv_bfloat16* Ash = Wlo + 400 * WLOSTR;            // [2][32][232]
    float* c1sh   = (float*)(Ash + 2 * ABUF);           // [100][33]
    float* w2i    = c1sh + CELL * CSTRIDE;              // [100][4]
    float* wih_sh = w2i + 400;                          // [100][4]
    float* bsum_sh= wih_sh + 400;                       // [100][4]
    float* xsh    = bsum_sh + 400;                      // [32] (future phase)

    const int tid    = threadIdx.x;
    const int bglob0 = blockIdx.x * NB;
    const int wid    = tid >> 5;
    const int lane   = tid & 31;

    // ================= staging =================
    for (int idx = tid; idx < 400 * WSTR; idx += THREADS) {
        int n = idx / WSTR, kk = idx - n * WSTR;
        int u = n >> 2, k = n & 3;
        float w = (kk < CELL) ? W_hh1[(k * CELL + u) * CELL + kk] : 0.0f;
        Whi[idx] = __float2bfloat16(w);
    }
    for (int idx = tid; idx < 400 * WLOSTR; idx += THREADS) {
        int n = idx / WLOSTR, kk = idx - n * WLOSTR;
        int u = n >> 2, k = n & 3;
        float lo = 0.0f;
        if (kk < CELL) {
            float w = W_hh1[(k * CELL + u) * CELL + kk];
            lo = w - __bfloat162float(__float2bfloat16(w));
        }
        Wlo[idx] = __float2bfloat16(lo);
    }
    for (int idx = tid; idx < 2 * ABUF; idx += THREADS)
        Ash[idx] = __float2bfloat16(0.0f);
    for (int idx = tid; idx < CELL * CSTRIDE; idx += THREADS) c1sh[idx] = 0.0f;
    for (int idx = tid; idx < 400; idx += THREADS) {
        int u = idx >> 2, k = idx & 3;
        w2i[idx]    = W_ih2[k * CELL + u];
        wih_sh[idx] = W_ih1[k * CELL + u];
        bsum_sh[idx]= b_ih1[k * CELL + u] + b_hh1[k * CELL + u];
    }
    if (tid < NB) xsh[tid] = 0.0f;

    // ================= per-thread setup =================
    const bool cw  = (wid < 20);                // compute warp
    const bool l2w = (wid >= 20);               // layer-2 warps (20, 21)
    const int  grp = cw ? (wid / 10) : (wid - 20);   // 0 or 1
    const int  g   = cw ? (wid % 10) : 0;       // n-group (0..9)
    const int  q   = lane & 3;
    const int  pp  = q & 1;                     // 0: holds (i,f); 1: holds (g,o)
    const int  rowbase = lane >> 2;
    const int  rowm = grp * 16 + rowbase + (pp ? 8 : 0);  // this thread's batch row

    const int barMid = 1 + 2 * grp;             // 1 or 3
    const int barEnd = 2 + 2 * grp;             // 2 or 4

    // ldmatrix lane addresses (byte offsets precomputed)
    const uint32_t Au32  = smem_u32(Ash);
    const uint32_t Whi32 = smem_u32(Whi);
    const uint32_t Wlo32 = smem_u32(Wlo);
    uint32_t aaddr[2], bph[2], bpl[2], bs4h = 0, bs4l = 0;
    if (cw) {
        // A: 16 rows of own m-tile (= group), both k-halves, per buffer
        const uint32_t arow = ((grp * 16 + (lane & 15)) * ASTRIDE + (lane >> 4) * 8) * 2;
        aaddr[0] = Au32 + arow;
        aaddr[1] = Au32 + ABUF * 2 + arow;
        // B pairs: x4 loads n-tiles (5g+2j, 5g+2j+1), both k-halves
        const int sub = lane >> 3, l8 = lane & 7;
        const int ntoff = sub >> 1, khalf = sub & 1;
        #pragma unroll
        for (int j = 0; j < 2; j++) {
            int nt = 5 * g + 2 * j + ntoff;
            bph[j] = Whi32 + ((8 * nt + l8) * WSTR   + khalf * 8) * 2;
            bpl[j] = Wlo32 + ((8 * nt + l8) * WLOSTR + khalf * 8) * 2;
        }
        // B single: n-tile 5g+4 (x2: lanes 0-15, two k-halves)
        const int l4 = lane & 15;
        bs4h = Whi32 + ((8 * (5 * g + 4) + (l4 & 7)) * WSTR   + ((l4 >> 3) & 1) * 8) * 2;
        bs4l = Wlo32 + ((8 * (5 * g + 4) + (l4 & 7)) * WLOSTR + ((l4 >> 3) & 1) * 8) * 2;
    }

    // layer-2 lanes: warp 20 -> rows 0-15, warp 21 -> rows 16-31
    const bool l2act = l2w && (lane < 16);
    const int  brow  = grp * 16 + lane;         // batch row for l2 lane
    float whh2[4], b2c[4];
    float h2 = 0.0f, c2 = 0.0f;
    if (l2act) {
        #pragma unroll
        for (int k = 0; k < 4; k++) {
            whh2[k] = W_hh2[k];
            b2c[k]  = b_ih2[k] + b_hh2[k];
        }
    }

    float c1r[5];
    #pragma unroll
    for (int i = 0; i < 5; i++) c1r[i] = 0.0f;

    __syncthreads();

    // ================= main loop =================
    const int TOT = T + FUT;
    for (int t = 0; t < TOT; ++t) {
        const bool fut = (t >= T);
        const int p = t & 1;          // A buffer holding h[t-1]
        float d[5][4];
        float xv = 0.0f;

        if (cw) {
            // ---- x prefetch (observed): LDG before the alternation gate ----
            if (!fut) {
                xv = __ldg(input + (size_t)t * Btot + bglob0 + rowm);
            }

            // ---- anti-phase gate: serialize the two groups' GEMMs ----
            if (grp == 0) { if (t > 0) BARSYNC(6, 640); }
            else          { BARSYNC(5, 640); }

            // ---- fused split-bf16 GEMM on h[t-1] (A buffer p, own rows) ----
            #pragma unroll
            for (int i = 0; i < 5; i++)
                #pragma unroll
                for (int r = 0; r < 4; r++) d[i][r] = 0.0f;

            const uint32_t ah_base = aaddr[p];

            #pragma unroll
            for (int kk = 0; kk < 7; kk++) {
                const uint32_t off = (uint32_t)(kk * 32);   // 16 cols * 2B

                uint32_t ah[4], al[4];
                LDSM_X4(ah[0], ah[1], ah[2], ah[3], ah_base + off);
                LDSM_X4(al[0], al[1], al[2], al[3], ah_base + ALO * 2 + off);

                #pragma unroll
                for (int j = 0; j < 2; j++) {
                    uint32_t bh0, bh1, bh2, bh3;
                    LDSM_X4(bh0, bh1, bh2, bh3, bph[j] + off);
                    MMA16816(d[2*j],   ah[0], ah[1], ah[2], ah[3], bh0, bh1);
                    MMA16816(d[2*j],   al[0], al[1], al[2], al[3], bh0, bh1);
                    MMA16816(d[2*j+1], ah[0], ah[1], ah[2], ah[3], bh2, bh3);
                    MMA16816(d[2*j+1], al[0], al[1], al[2], al[3], bh2, bh3);
                    uint32_t bl0, bl1, bl2r, bl3;
                    LDSM_X4(bl0, bl1, bl2r, bl3, bpl[j] + off);
                    MMA16816(d[2*j],   ah[0], ah[1], ah[2], ah[3], bl0, bl1);
                    MMA16816(d[2*j+1], ah[0], ah[1], ah[2], ah[3], bl2r, bl3);
                }
                {
                    uint32_t b0, b1;
                    LDSM_X2(b0, b1, bs4h + off);
                    MMA16816(d[4], ah[0], ah[1], ah[2], ah[3], b0, b1);
                    MMA16816(d[4], al[0], al[1], al[2], al[3], b0, b1);
                    uint32_t c0, c1v;
                    LDSM_X2(c0, c1v, bs4l + off);
                    MMA16816(d[4], ah[0], ah[1], ah[2], ah[3], c0, c1v);
                }
            }

            // signal: this group's GEMM done
            if (grp == 0) BARARRIVE(5, 640);
            else          BARARRIVE(6, 640);

            // mid barrier: own l2 warp has finished its c1 reads / xsh write
            BARSYNC(barMid, 352);

            if (fut) xv = xsh[rowm];

            // ---- epilogue: writes A buffer p^1 and c1 (own rows) ----
            __nv_bfloat16* aw = Ash + (p ^ 1) * ABUF + rowm * ASTRIDE;
            #pragma unroll
            for (int i = 0; i < 5; i++) {
                const int u = 2 * (5 * g + i) + (q >> 1);
                float* dd = d[i];
                // exchange with lane^1: even keeps row r, odd keeps row r+8
                float g0 = pp ? dd[0] : dd[2];
                float g1 = pp ? dd[1] : dd[3];
                float r0 = __shfl_xor_sync(0xffffffffu, g0, 1);
                float r1 = __shfl_xor_sync(0xffffffffu, g1, 1);
                float gi, gf, gg, go;
                if (!pp) { gi = dd[0]; gf = dd[1]; gg = r0;    go = r1;    }
                else     { gi = r0;    gf = r1;    gg = dd[2]; go = dd[3]; }

                const float4 bs = *(const float4*)(bsum_sh + u * 4);
                const float4 wi = *(const float4*)(wih_sh + u * 4);
                float pi = fmaf(xv, wi.x, gi + bs.x);
                float pf = fmaf(xv, wi.y, gf + bs.y);
                float pg = fmaf(xv, wi.z, gg + bs.z);
                float po = fmaf(xv, wi.w, go + bs.w);
                float c = sigm_fast(pf) * c1r[i] + sigm_fast(pi) * tanh_hw(pg);
                c1r[i] = c;
                float h = sigm_fast(po) * tanh_hw(c);

                c1sh[u * CSTRIDE + rowm] = c;
                __nv_bfloat16 hh = __float2bfloat16(h);
                aw[u] = hh;
                aw[ALO + u] = __float2bfloat16(h - __bfloat162float(hh));
            }

            // end-of-step: A[p^1], c1 published to own group + own l2 warp
            BARSYNC(barEnd, 352);
        } else if (l2w) {
            // ---- layer-2 for step t-1 (own 16 batch rows) ----
            if (t > 0 && l2act) {
                const int tt = t - 1;
                const float* cp = c1sh + brow;
                float di = 0.f, df = 0.f, dg = 0.f, dz = 0.f;
                #pragma unroll 10
                for (int uu = 0; uu < CELL; uu++) {
                    float cv  = cp[uu * CSTRIDE];
                    float4 w4 = *(const float4*)(w2i + uu * 4);
                    di = fmaf(cv, w4.x, di);
                    df = fmaf(cv, w4.y, df);
                    dg = fmaf(cv, w4.z, dg);
                    dz = fmaf(cv, w4.w, dz);
                }
                float pi = fmaf(h2, whh2[0], di + b2c[0]);
                float pf = fmaf(h2, whh2[1], df + b2c[1]);
                float pg = fmaf(h2, whh2[2], dg + b2c[2]);
                float po = fmaf(h2, whh2[3], dz + b2c[3]);
                float c  = sigm(pf) * c2 + sigm(pi) * tanh_f(pg);
                c2 = c;
                h2 = sigm(po) * tanh_f(c);
                if (t >= T) xsh[brow] = c;              // x for future step t
                if (tt >= T) out[(size_t)(bglob0 + brow) * FUT + (tt - T)] = c;
            }
            BARARRIVE(barMid, 352);   // c1 reads + xsh write done
            BARSYNC(barEnd, 352);     // wait for epilogue(t) before next reads
        }
    }

    // drain: layer-2 for the final step TOT-1
    if (l2act) {
        const int tt = TOT - 1;
        const float* cp = c1sh + brow;
        float di = 0.f, df = 0.f, dg = 0.f, dz = 0.f;
        #pragma unroll 10
        for (int uu = 0; uu < CELL; uu++) {
            float cv  = cp[uu * CSTRIDE];
            float4 w4 = *(const float4*)(w2i + uu * 4);
            di = fmaf(cv, w4.x, di);
            df = fmaf(cv, w4.y, df);
            dg = fmaf(cv, w4.z, dg);
            dz = fmaf(cv, w4.w, dz);
        }
        float pi = fmaf(h2, whh2[0], di + b2c[0]);
        float pf = fmaf(h2, whh2[1], df + b2c[1]);
        float pg = fmaf(h2, whh2[2], dg + b2c[2]);
        float po = fmaf(h2, whh2[3], dz + b2c[3]);
        float c  = sigm(pf) * c2 + sigm(pi) * tanh_f(pg);
        out[(size_t)(bglob0 + brow) * FUT + (tt - T)] = c;
    }
}

extern "C" void kernel_launch(void* const* d_in, const int* in_sizes, int n_in,
                              void* d_out, int out_size)
{
    const float* input = (const float*)d_in[0];
    const float* W_ih1 = (const float*)d_in[1];
    const float* W_hh1 = (const float*)d_in[2];
    const float* b_ih1 = (const float*)d_in[3];
    const float* b_hh1 = (const float*)d_in[4];
    const float* W_ih2 = (const float*)d_in[5];
    const float* W_hh2 = (const float*)d_in[6];
    const float* b_ih2 = (const float*)d_in[7];
    const float* b_hh2 = (const float*)d_in[8];
    float* out = (float*)d_out;

    const int Btot = 4096;
    const int T    = in_sizes[0] / Btot;   // 512
    const int FUT  = out_size   / Btot;    // 64

    const int smem = (400 * WSTR + 400 * WLOSTR + 2 * ABUF) * 2  // bf16 regions
                   + (CELL * CSTRIDE + 400 * 3 + NB) * 4;        // fp32 regions
                   // = (48000+41600+14848)*2 + (3300+1200+32)*4 = 227,024 B

    cudaFuncSetAttribute(tsrnn_kernel,
                         cudaFuncAttributeMaxDynamicSharedMemorySize, smem);

    tsrnn_kernel<<<Btot / NB, THREADS, smem>>>(
        input, W_ih1, W_hh1, b_ih1, b_hh1,
        W_ih2, W_hh2, b_ih2, b_hh2,
        out, T, FUT, Btot);
}